// round 6
// baseline (speedup 1.0000x reference)
#include <cuda_runtime.h>
#include <cuda_bf16.h>
#include <cstdint>

#define NB_B 64
#define NN   4096
#define DD   16
#define CC   1024

// ---- IMMA GEMM tiling ----
#define BM 128
#define BN 128
#define BKB 64               // K bytes per stage (64 s8)
#define STAGES 4
#define KTILES 64            // 4096 / 64
#define TILEB (128*64)       // one operand tile: 128 rows * 64 B = 8 KB
#define STGB  (2*TILEB)      // 16 KB per stage
#define DSMEM (STAGES*STGB)  // 64 KB

// adj quant: adj in [0, 2/4096); q = round(adj * 127*4096/2)
#define ADJ_Q   260096.0f
// dequant: s_adj * s_col = (2/4096/127) * (cmax/127)
#define SCONST  (2.0f / (4096.0f * 127.0f * 127.0f))

// ---- scratch ----
__device__ float   g_H [(size_t)NN*CC];     // fp32 H (identity path)
__device__ float   g_O [(size_t)NN*CC];     // layer output
__device__ char    g_adjq[(size_t)NN*NN];   // adj s8
__device__ char    g_HTq[(size_t)CC*NN];    // H^T s8 [c][m]
__device__ int     g_cmax[3*1024];          // per-layer per-column |h|max (float bits)

__device__ __forceinline__ uint32_t smem_u32(const void* p) {
    uint32_t a;
    asm("{ .reg .u64 t; cvta.to.shared.u64 t, %1; cvt.u32.u64 %0, t; }" : "=r"(a) : "l"(p));
    return a;
}
__device__ __forceinline__ void cp16(uint32_t dst, const void* src) {
    asm volatile("cp.async.cg.shared.global [%0], [%1], 16;" :: "r"(dst), "l"(src) : "memory");
}
// 64B rows, 4x16B chunks; conflict-free for ldmatrix phases
__device__ __forceinline__ uint32_t swz(int r, int q) {
    return (uint32_t)((r << 6) + ((q ^ ((r >> 1) & 3)) << 4));
}

#define LDSM4(R, addr) \
    asm volatile("ldmatrix.sync.aligned.m8n8.x4.shared.b16 {%0,%1,%2,%3}, [%4];" \
        : "=r"((R)[0]), "=r"((R)[1]), "=r"((R)[2]), "=r"((R)[3]) : "r"(addr))

#define IMMA(C, A_, B0, B1) \
    asm volatile("mma.sync.aligned.m16n8k32.row.col.s32.s8.s8.s32 " \
        "{%0,%1,%2,%3}, {%4,%5,%6,%7}, {%8,%9}, {%0,%1,%2,%3};" \
        : "+r"((C)[0]), "+r"((C)[1]), "+r"((C)[2]), "+r"((C)[3]) \
        : "r"((A_)[0]), "r"((A_)[1]), "r"((A_)[2]), "r"((A_)[3]), "r"(B0), "r"(B1))

// ================= clear colmax =================
__global__ void clear_cmax_kernel(int* cm) {
    cm[blockIdx.x * 1024 + threadIdx.x] = 0;
}

// ================= adj fp32 -> s8 =================
__global__ void cvt_adj_kernel(const float* __restrict__ A, char* __restrict__ Aq) {
    size_t idx = (size_t)blockIdx.x * 256 + threadIdx.x;   // 16 elems / thread
    const float4* src = reinterpret_cast<const float4*>(A) + idx * 4;
    uint32_t w[4];
#pragma unroll
    for (int j = 0; j < 4; j++) {
        float4 v = src[j];
        int q0 = __float2int_rn(v.x * ADJ_Q), q1 = __float2int_rn(v.y * ADJ_Q);
        int q2 = __float2int_rn(v.z * ADJ_Q), q3 = __float2int_rn(v.w * ADJ_Q);
        w[j] = (uint32_t)(q0 & 255) | ((uint32_t)(q1 & 255) << 8) |
               ((uint32_t)(q2 & 255) << 16) | ((uint32_t)(q3 & 255) << 24);
    }
    reinterpret_cast<uint4*>(Aq)[idx] = make_uint4(w[0], w[1], w[2], w[3]);
}

// ===== lin: h = lrelu(X@W) -> H fp32 [m,c]; per-column absmax atomics =====
// tile: 32 m x 32 c. grid (CC/32, NN/32), 256 thr.
__global__ __launch_bounds__(256)
void lin_kernel(const float* __restrict__ X, const float* __restrict__ W,
                float* __restrict__ H, int* __restrict__ cmax, int mode) {
    __shared__ float sW[DD][DD];
    __shared__ float sX[2][32][DD];
    __shared__ int   sMax[32];

    const int t = threadIdx.x;
    const int c0 = blockIdx.x * 32, m0 = blockIdx.y * 32, b0 = c0 >> 4;

    if (t < 32) sMax[t] = 0;
    sW[t >> 4][t & 15] = W[t];
    {
        int bloc = t >> 7, m = (t >> 2) & 31, seg = t & 3;
        const float* xp = mode
            ? (X + (size_t)(m0 + m) * CC + (size_t)(b0 + bloc) * DD + seg * 4)
            : (X + ((size_t)(b0 + bloc) * NN + (m0 + m)) * DD + seg * 4);
        float4 v = *reinterpret_cast<const float4*>(xp);
        sX[bloc][m][seg*4]   = v.x; sX[bloc][m][seg*4+1] = v.y;
        sX[bloc][m][seg*4+2] = v.z; sX[bloc][m][seg*4+3] = v.w;
    }
    __syncthreads();

    {
        int m = t >> 3, quad = t & 7;
        int bloc = quad >> 2;
        int e0 = (quad & 3) * 4;
        float h[4] = {0.f, 0.f, 0.f, 0.f};
#pragma unroll
        for (int d = 0; d < DD; d++) {
            float xd = sX[bloc][m][d];
#pragma unroll
            for (int j = 0; j < 4; j++) h[j] = fmaf(xd, sW[d][e0 + j], h[j]);
        }
#pragma unroll
        for (int j = 0; j < 4; j++) h[j] = h[j] > 0.f ? h[j] : 0.2f * h[j];

        *reinterpret_cast<float4*>(H + (size_t)(m0 + m) * CC + c0 + quad * 4) =
            make_float4(h[0], h[1], h[2], h[3]);
#pragma unroll
        for (int j = 0; j < 4; j++)
            atomicMax(&sMax[quad * 4 + j], __float_as_int(fabsf(h[j])));
    }
    __syncthreads();
    if (t < 32) atomicMax(&cmax[c0 + t], sMax[t]);
}

// ===== qtr: H fp32 [m,c] -> HTq s8 [c][m], per-column scale =====
// tile: 128 m x 32 c. grid (NN/128, CC/32), 256 thr.
__global__ __launch_bounds__(256)
void qtr_kernel(const float* __restrict__ H, const int* __restrict__ cmax,
                char* __restrict__ HTq) {
    __shared__ float sm[32][132];
    const int t = threadIdx.x;
    const int m0 = blockIdx.x * 128, c0 = blockIdx.y * 32;

    {
        int m = t >> 3, c4 = t & 7;
#pragma unroll
        for (int i = 0; i < 4; i++) {
            float4 v = *reinterpret_cast<const float4*>(
                H + (size_t)(m0 + m + 32 * i) * CC + c0 + c4 * 4);
            sm[c4*4+0][m + 32*i] = v.x; sm[c4*4+1][m + 32*i] = v.y;
            sm[c4*4+2][m + 32*i] = v.z; sm[c4*4+3][m + 32*i] = v.w;
        }
    }
    __syncthreads();
    {
        int c = t >> 3, s = t & 7;
        float mx = __int_as_float(cmax[c0 + c]);
        float sc = 127.0f / fmaxf(mx, 1e-30f);
        uint32_t w[4];
#pragma unroll
        for (int j = 0; j < 4; j++) {
            int q0 = __float2int_rn(sm[c][s*16 + j*4 + 0] * sc);
            int q1 = __float2int_rn(sm[c][s*16 + j*4 + 1] * sc);
            int q2 = __float2int_rn(sm[c][s*16 + j*4 + 2] * sc);
            int q3 = __float2int_rn(sm[c][s*16 + j*4 + 3] * sc);
            w[j] = (uint32_t)(q0 & 255) | ((uint32_t)(q1 & 255) << 8) |
                   ((uint32_t)(q2 & 255) << 16) | ((uint32_t)(q3 & 255) << 24);
        }
        *reinterpret_cast<uint4*>(HTq + (size_t)(c0 + c) * NN + m0 + s * 16) =
            make_uint4(w[0], w[1], w[2], w[3]);
    }
}

// ================= IMMA GEMM: out = dequant(adjq@HTq) + H =================
// 128 threads, 4 warps 2x2, warp tile 64x64, BK=64 s8, 4 stages, 2 CTAs/SM.
__global__ __launch_bounds__(128, 2)
void gemm_imma_kernel(const char* __restrict__ Aq,    // [4096,4096] s8
                      const char* __restrict__ Bq,    // [1024,4096] s8 (H^T)
                      const float* __restrict__ Hf,   // [4096,1024] fp32
                      const int* __restrict__ cmax,   // [1024] float bits
                      float* __restrict__ Cout, float* __restrict__ Dout,
                      int final_layer) {
    extern __shared__ char dsm[];
    const uint32_t sm = smem_u32(dsm);
    const int tid = threadIdx.x, wid = tid >> 5, l = tid & 31;
    const int bx = blockIdx.x, by = blockIdx.y;
    const int wm = wid >> 1, wn = wid & 1;

    const char* gA = Aq + (size_t)by * BM * NN;
    const char* gB = Bq + (size_t)bx * BN * NN;

    // producer: 8 cp16/thread/stage (4 A + 4 B)
    const int r0 = tid >> 2, q0 = tid & 3;      // r0: 0..31
    uint32_t offL[4];
    size_t gOff[4];
#pragma unroll
    for (int i = 0; i < 4; i++) {
        offL[i] = swz(r0 + 32 * i, q0);
        gOff[i] = (size_t)(r0 + 32 * i) * NN + q0 * 16;
    }

#define LOAD_STAGE(s, kt) { \
    uint32_t sa = sm + (uint32_t)(s) * STGB; \
    const char* ga = gA + (size_t)(kt) * BKB; \
    const char* gb = gB + (size_t)(kt) * BKB; \
    _Pragma("unroll") \
    for (int i_ = 0; i_ < 4; i_++) { \
        cp16(sa + offL[i_],         ga + gOff[i_]); \
        cp16(sa + TILEB + offL[i_], gb + gOff[i_]); } }

    // ldmatrix lane coords (x4 over 16 rows x 32B: tiles row-lo/hi x byte-lo/hi)
    const int lrow = ((l >> 3) & 1) * 8 + (l & 7);   // 0..15
    const int lq   = l >> 4;                          // 0..1

    int acc[4][8][4];
#pragma unroll
    for (int i = 0; i < 4; i++)
#pragma unroll
        for (int j = 0; j < 8; j++)
#pragma unroll
            for (int k = 0; k < 4; k++) acc[i][j][k] = 0;

#pragma unroll
    for (int s = 0; s < STAGES - 1; s++) {
        LOAD_STAGE(s, s);
        asm volatile("cp.async.commit_group;" ::: "memory");
    }
    asm volatile("cp.async.wait_group %0;" :: "n"(STAGES - 2) : "memory");
    __syncthreads();

    uint32_t a[2][4][4], b[2][4][4];

#pragma unroll 1
    for (int kt = 0; kt < KTILES; kt++) {
        int pf = kt + STAGES - 1;
        if (pf < KTILES) { LOAD_STAGE(pf & (STAGES - 1), pf); }
        asm volatile("cp.async.commit_group;" ::: "memory");

        const uint32_t base = sm + (uint32_t)(kt & (STAGES - 1)) * STGB;

        // ks=0 fragments
#pragma unroll
        for (int mi = 0; mi < 4; mi++)
            LDSM4(a[0][mi], base + swz(wm * 64 + mi * 16 + lrow, lq));
#pragma unroll
        for (int nb = 0; nb < 4; nb++)
            LDSM4(b[0][nb], base + TILEB + swz(wn * 64 + nb * 16 + lrow, lq));

#pragma unroll
        for (int ks = 0; ks < 2; ks++) {
            int cur = ks & 1, nxt = cur ^ 1;
            if (ks == 0) {
#pragma unroll
                for (int mi = 0; mi < 4; mi++)
                    LDSM4(a[1][mi], base + swz(wm * 64 + mi * 16 + lrow, 2 + lq));
#pragma unroll
                for (int nb = 0; nb < 4; nb++)
                    LDSM4(b[1][nb], base + TILEB + swz(wn * 64 + nb * 16 + lrow, 2 + lq));
            }
#pragma unroll
            for (int mi = 0; mi < 4; mi++) {
#pragma unroll
                for (int nb = 0; nb < 4; nb++) {
                    const uint32_t* bb = b[cur][nb];
                    IMMA(acc[mi][2*nb],   a[cur][mi], bb[0], bb[2]);
                    IMMA(acc[mi][2*nb+1], a[cur][mi], bb[1], bb[3]);
                }
            }
        }
        asm volatile("cp.async.wait_group %0;" :: "n"(STAGES - 2) : "memory");
        __syncthreads();
    }

    // ---- epilogue: dequant + H (fp32 identity), store ----
    const int m0 = by * BM + wm * 64;
    const int c0 = bx * BN + wn * 64;
#pragma unroll
    for (int mi = 0; mi < 4; mi++) {
#pragma unroll
        for (int ni = 0; ni < 8; ni++) {
            int m = m0 + mi * 16 + (l >> 2);
            int c = c0 + ni * 8 + 2 * (l & 3);
            float s0 = __int_as_float(cmax[c])     * SCONST;
            float s1 = __int_as_float(cmax[c + 1]) * SCONST;
            float2 i0 = *reinterpret_cast<const float2*>(Hf + (size_t)m * CC + c);
            float2 i1 = *reinterpret_cast<const float2*>(Hf + (size_t)(m + 8) * CC + c);
            float2 o0 = make_float2((float)acc[mi][ni][0] * s0 + i0.x,
                                    (float)acc[mi][ni][1] * s1 + i0.y);
            float2 o1 = make_float2((float)acc[mi][ni][2] * s0 + i1.x,
                                    (float)acc[mi][ni][3] * s1 + i1.y);
            if (final_layer) {
                int bq = c >> 4, d = c & 15;
                *reinterpret_cast<float2*>(Dout + ((size_t)bq * NN + m) * DD + d) = o0;
                *reinterpret_cast<float2*>(Dout + ((size_t)bq * NN + m + 8) * DD + d) = o1;
            } else {
                *reinterpret_cast<float2*>(Cout + (size_t)m * CC + c) = o0;
                *reinterpret_cast<float2*>(Cout + (size_t)(m + 8) * CC + c) = o1;
            }
        }
    }
#undef LOAD_STAGE
}

// ================= launch =================
extern "C" void kernel_launch(void* const* d_in, const int* in_sizes, int n_in,
                              void* d_out, int out_size) {
    const float* x   = (const float*)d_in[0];
    const float* adj = (const float*)d_in[1];
    const float* W0  = (const float*)d_in[3];
    const float* W1  = (const float*)d_in[4];
    const float* W2  = (const float*)d_in[5];
    float* out = (float*)d_out;

    float *pH, *pO;
    char *pAq, *pHTq;
    int  *pCM;
    cudaGetSymbolAddress((void**)&pH,   g_H);
    cudaGetSymbolAddress((void**)&pO,   g_O);
    cudaGetSymbolAddress((void**)&pAq,  g_adjq);
    cudaGetSymbolAddress((void**)&pHTq, g_HTq);
    cudaGetSymbolAddress((void**)&pCM,  g_cmax);

    cudaFuncSetAttribute(gemm_imma_kernel, cudaFuncAttributeMaxDynamicSharedMemorySize, DSMEM);

    dim3 lgrid(CC / 32, NN / 32);                  // (32, 128)
    dim3 qgrid(NN / 128, CC / 32);                 // (32, 32)
    dim3 ggrid(CC / BN, NN / BM);                  // (8, 32)

    clear_cmax_kernel<<<3, 1024>>>(pCM);
    cvt_adj_kernel<<<(int)(((size_t)NN * NN) / (256 * 16)), 256>>>(adj, pAq);

    lin_kernel<<<lgrid, 256>>>(x, W0, pH, pCM, 0);
    qtr_kernel<<<qgrid, 256>>>(pH, pCM, pHTq);
    gemm_imma_kernel<<<ggrid, 128, DSMEM>>>(pAq, pHTq, pH, pCM, pO, nullptr, 0);

    lin_kernel<<<lgrid, 256>>>(pO, W1, pH, pCM + 1024, 1);
    qtr_kernel<<<qgrid, 256>>>(pH, pCM + 1024, pHTq);
    gemm_imma_kernel<<<ggrid, 128, DSMEM>>>(pAq, pHTq, pH, pCM + 1024, pO, nullptr, 0);

    lin_kernel<<<lgrid, 256>>>(pO, W2, pH, pCM + 2048, 1);
    qtr_kernel<<<qgrid, 256>>>(pH, pCM + 2048, pHTq);
    gemm_imma_kernel<<<ggrid, 128, DSMEM>>>(pAq, pHTq, pH, pCM + 2048, nullptr, out, 1);
}

// round 7
// speedup vs baseline: 2.4470x; 2.4470x over previous
#include <cuda_runtime.h>
#include <cuda_bf16.h>
#include <cstdint>

#define NN   4096
#define DD   16
#define CC   1024

// ---- GEMM tiling ----
#define BM 128
#define BN 256
#define KTILES 128            // K=4096 / BK=32
#define ASTG 8192             // A stage: 128 rows x 64 B
#define BSTG 16384            // B stage: 32 k-rows x 512 B
#define STGB (ASTG + BSTG)    // 24 KB
#define STAGES 4
#define DSMEM (STAGES * STGB) // 96 KB

// ---- scratch ----
__device__ float          g_H [(size_t)NN*CC];   // fp32 H (identity path)
__device__ float          g_O [(size_t)NN*CC];   // layer output
__device__ __nv_bfloat16  g_adjb[(size_t)NN*NN]; // adj bf16 [m][k]
__device__ __nv_bfloat16  g_Hb[(size_t)NN*CC];   // H bf16 [m][c] (B operand, k-major)

__device__ __forceinline__ uint32_t smem_u32(const void* p) {
    uint32_t a;
    asm("{ .reg .u64 t; cvta.to.shared.u64 t, %1; cvt.u32.u64 %0, t; }" : "=r"(a) : "l"(p));
    return a;
}
__device__ __forceinline__ void cp16(uint32_t dst, const void* src) {
    asm volatile("cp.async.cg.shared.global [%0], [%1], 16;" :: "r"(dst), "l"(src) : "memory");
}
// A: 64B rows, 4 chunks; proven conflict-free
__device__ __forceinline__ uint32_t swzA(int r, int q) {
    return (uint32_t)((r << 6) + ((q ^ ((r >> 1) & 3)) << 4));
}
// B: 512B rows (k), 32 chunks; q ^= (k&7)<<1
__device__ __forceinline__ uint32_t swzB(int k, int q) {
    return (uint32_t)((k << 9) + ((q ^ ((k & 7) << 1)) << 4));
}

#define LDSM4(R, addr) \
    asm volatile("ldmatrix.sync.aligned.m8n8.x4.shared.b16 {%0,%1,%2,%3}, [%4];" \
        : "=r"((R)[0]), "=r"((R)[1]), "=r"((R)[2]), "=r"((R)[3]) : "r"(addr))
#define LDSM4T(R, addr) \
    asm volatile("ldmatrix.sync.aligned.m8n8.x4.trans.shared.b16 {%0,%1,%2,%3}, [%4];" \
        : "=r"((R)[0]), "=r"((R)[1]), "=r"((R)[2]), "=r"((R)[3]) : "r"(addr))

#define MMA(C, A_, B0, B1) \
    asm volatile("mma.sync.aligned.m16n8k16.row.col.f32.bf16.bf16.f32 " \
        "{%0,%1,%2,%3}, {%4,%5,%6,%7}, {%8,%9}, {%0,%1,%2,%3};" \
        : "+f"((C)[0]), "+f"((C)[1]), "+f"((C)[2]), "+f"((C)[3]) \
        : "r"((A_)[0]), "r"((A_)[1]), "r"((A_)[2]), "r"((A_)[3]), "r"(B0), "r"(B1))

// ================= adj fp32 -> bf16 =================
__global__ void cvt_adj_kernel(const float* __restrict__ A, __nv_bfloat16* __restrict__ Ab) {
    size_t idx = (size_t)blockIdx.x * 256 + threadIdx.x;
    const float4* src = reinterpret_cast<const float4*>(A) + idx * 2;
    float4 a = src[0], b = src[1];
    union { __nv_bfloat162 h[4]; uint4 u; } pk;
    pk.h[0] = __floats2bfloat162_rn(a.x, a.y);
    pk.h[1] = __floats2bfloat162_rn(a.z, a.w);
    pk.h[2] = __floats2bfloat162_rn(b.x, b.y);
    pk.h[3] = __floats2bfloat162_rn(b.z, b.w);
    reinterpret_cast<uint4*>(Ab)[idx] = pk.u;
}

// ===== lin: h = lrelu(X@W) -> H fp32 [m,c] AND Hb bf16 [m,c] (no transpose) =====
// tile: 32 m x 32 c. grid (CC/32, NN/32), 256 thr.
__global__ __launch_bounds__(256)
void lin_kernel(const float* __restrict__ X, const float* __restrict__ W,
                float* __restrict__ H, __nv_bfloat16* __restrict__ Hb, int mode) {
    __shared__ float sW[DD][DD];
    __shared__ float sX[2][32][DD];

    const int t = threadIdx.x;
    const int c0 = blockIdx.x * 32, m0 = blockIdx.y * 32, b0 = c0 >> 4;

    sW[t >> 4][t & 15] = W[t];
    {
        int bloc = t >> 7, m = (t >> 2) & 31, seg = t & 3;
        const float* xp = mode
            ? (X + (size_t)(m0 + m) * CC + (size_t)(b0 + bloc) * DD + seg * 4)
            : (X + ((size_t)(b0 + bloc) * NN + (m0 + m)) * DD + seg * 4);
        float4 v = *reinterpret_cast<const float4*>(xp);
        sX[bloc][m][seg*4]   = v.x; sX[bloc][m][seg*4+1] = v.y;
        sX[bloc][m][seg*4+2] = v.z; sX[bloc][m][seg*4+3] = v.w;
    }
    __syncthreads();

    {
        int m = t >> 3, quad = t & 7;
        int bloc = quad >> 2;
        int e0 = (quad & 3) * 4;
        float h[4] = {0.f, 0.f, 0.f, 0.f};
#pragma unroll
        for (int d = 0; d < DD; d++) {
            float xd = sX[bloc][m][d];
#pragma unroll
            for (int j = 0; j < 4; j++) h[j] = fmaf(xd, sW[d][e0 + j], h[j]);
        }
#pragma unroll
        for (int j = 0; j < 4; j++) h[j] = h[j] > 0.f ? h[j] : 0.2f * h[j];

        size_t off = (size_t)(m0 + m) * CC + c0 + quad * 4;
        *reinterpret_cast<float4*>(H + off) = make_float4(h[0], h[1], h[2], h[3]);
        union { __nv_bfloat162 p[2]; uint2 u; } pk;
        pk.p[0] = __floats2bfloat162_rn(h[0], h[1]);
        pk.p[1] = __floats2bfloat162_rn(h[2], h[3]);
        *reinterpret_cast<uint2*>(Hb + off) = pk.u;
    }
}

// ================= warp-specialized HMMA GEMM: out = adj@H + H =================
// 288 threads: warps 0-7 consumers (2x4 grid, 64x64 tiles), warp 8 producer.
// CTA tile 128x256; grid (4, 32) = 128 CTAs; 1 CTA/SM.
__global__ __launch_bounds__(288, 1)
void gemm_ws_kernel(const __nv_bfloat16* __restrict__ Ab,   // [4096,4096] bf16
                    const __nv_bfloat16* __restrict__ Hb,   // [4096,1024] bf16 (B, k-major)
                    const float* __restrict__ Hf,           // [4096,1024] fp32
                    float* __restrict__ Cout, float* __restrict__ Dout,
                    int final_layer) {
    extern __shared__ char dsm[];
    const uint32_t sm = smem_u32(dsm);
    const int tid = threadIdx.x, wid = tid >> 5, l = tid & 31;
    const int bx = blockIdx.x, by = blockIdx.y;

    const char* gA = (const char*)(Ab + (size_t)by * BM * NN);
    const char* gB = (const char*)Hb + (size_t)bx * BN * 2;

    // A: 512 chunks (16 iters), B: 1024 chunks... B rows=32, 32 chunks each (32 iters)
#define PROD_STAGE(sidx, kt) { \
    uint32_t sa = sm + (uint32_t)(sidx) * STGB; \
    const char* ga = gA + (size_t)(kt) * 64; \
    _Pragma("unroll") \
    for (int i_ = 0; i_ < 16; i_++) { \
        int r_ = i_ * 8 + (l >> 2), q_ = l & 3; \
        cp16(sa + swzA(r_, q_), ga + (size_t)r_ * 8192 + q_ * 16); } \
    uint32_t sb = sa + ASTG; \
    const char* gb = gB + (size_t)(kt) * 32 * 2048; \
    _Pragma("unroll") \
    for (int i_ = 0; i_ < 32; i_++) { \
        cp16(sb + swzB(i_, l), gb + (size_t)i_ * 2048 + l * 16); } }

    const bool producer = (wid == 8);
    const int wm = wid >> 2, wn = wid & 3;   // consumers only

    float acc[4][8][4];
#pragma unroll
    for (int i = 0; i < 4; i++)
#pragma unroll
        for (int j = 0; j < 8; j++)
#pragma unroll
            for (int k = 0; k < 4; k++) acc[i][j][k] = 0.0f;

    if (producer) {
#pragma unroll
        for (int s = 0; s < STAGES - 1; s++) {
            PROD_STAGE(s, s);
            asm volatile("cp.async.commit_group;" ::: "memory");
        }
        asm volatile("cp.async.wait_group %0;" :: "n"(STAGES - 2) : "memory");
    }
    __syncthreads();

    // consumer ldmatrix lane coords
    const int arow = wm * 64 + (l & 15);           // + mi*16
    const int aqh  = l >> 4;                        // k 16B half
    const int g    = l >> 3;
    const int bk   = (g & 1) * 8 + (l & 7);        // + ks*16
    const int bq   = wn * 8 + (g >> 1);            // + nb*2

    uint32_t a[2][4][4], b[2][4][4];

#pragma unroll 1
    for (int kt = 0; kt < KTILES; kt++) {
        if (producer) {
            int pf = kt + STAGES - 1;
            if (pf < KTILES) { PROD_STAGE((pf & (STAGES - 1)), pf); }
            asm volatile("cp.async.commit_group;" ::: "memory");
            asm volatile("cp.async.wait_group %0;" :: "n"(STAGES - 2) : "memory");
        } else {
            const uint32_t base  = sm + (uint32_t)(kt & (STAGES - 1)) * STGB;
            const uint32_t baseB = base + ASTG;
            // ks=0 fragments
#pragma unroll
            for (int mi = 0; mi < 4; mi++)
                LDSM4(a[0][mi], base + swzA(arow + mi * 16, aqh));
#pragma unroll
            for (int nb = 0; nb < 4; nb++)
                LDSM4T(b[0][nb], baseB + swzB(bk, bq + nb * 2));
#pragma unroll
            for (int ks = 0; ks < 2; ks++) {
                if (ks == 0) {   // prefetch ks=1
#pragma unroll
                    for (int mi = 0; mi < 4; mi++)
                        LDSM4(a[1][mi], base + swzA(arow + mi * 16, 2 + aqh));
#pragma unroll
                    for (int nb = 0; nb < 4; nb++)
                        LDSM4T(b[1][nb], baseB + swzB(16 + bk, bq + nb * 2));
                }
#pragma unroll
                for (int mi = 0; mi < 4; mi++) {
#pragma unroll
                    for (int nb = 0; nb < 4; nb++) {
                        const uint32_t* bb = b[ks][nb];
                        MMA(acc[mi][2*nb],   a[ks][mi], bb[0], bb[1]);
                        MMA(acc[mi][2*nb+1], a[ks][mi], bb[2], bb[3]);
                    }
                }
            }
        }
        __syncthreads();
    }

    // ---- epilogue (consumers): + H fp32 identity, store ----
    if (!producer) {
        const int m0 = by * BM + wm * 64;
        const int c0 = bx * BN + wn * 64;
#pragma unroll
        for (int mi = 0; mi < 4; mi++) {
#pragma unroll
            for (int ni = 0; ni < 8; ni++) {
                int m = m0 + mi * 16 + (l >> 2);
                int c = c0 + ni * 8 + 2 * (l & 3);
                float2 i0 = *reinterpret_cast<const float2*>(Hf + (size_t)m * CC + c);
                float2 i1 = *reinterpret_cast<const float2*>(Hf + (size_t)(m + 8) * CC + c);
                float2 o0 = make_float2(acc[mi][ni][0] + i0.x, acc[mi][ni][1] + i0.y);
                float2 o1 = make_float2(acc[mi][ni][2] + i1.x, acc[mi][ni][3] + i1.y);
                if (final_layer) {
                    int bq2 = c >> 4, d = c & 15;
                    *reinterpret_cast<float2*>(Dout + ((size_t)bq2 * NN + m) * DD + d) = o0;
                    *reinterpret_cast<float2*>(Dout + ((size_t)bq2 * NN + m + 8) * DD + d) = o1;
                } else {
                    *reinterpret_cast<float2*>(Cout + (size_t)m * CC + c) = o0;
                    *reinterpret_cast<float2*>(Cout + (size_t)(m + 8) * CC + c) = o1;
                }
            }
        }
    }
#undef PROD_STAGE
}

// ================= launch =================
extern "C" void kernel_launch(void* const* d_in, const int* in_sizes, int n_in,
                              void* d_out, int out_size) {
    const float* x   = (const float*)d_in[0];
    const float* adj = (const float*)d_in[1];
    const float* W0  = (const float*)d_in[3];
    const float* W1  = (const float*)d_in[4];
    const float* W2  = (const float*)d_in[5];
    float* out = (float*)d_out;

    float *pH, *pO;
    __nv_bfloat16 *pAb, *pHb;
    cudaGetSymbolAddress((void**)&pH,  g_H);
    cudaGetSymbolAddress((void**)&pO,  g_O);
    cudaGetSymbolAddress((void**)&pAb, g_adjb);
    cudaGetSymbolAddress((void**)&pHb, g_Hb);

    cudaFuncSetAttribute(gemm_ws_kernel, cudaFuncAttributeMaxDynamicSharedMemorySize, DSMEM);

    dim3 lgrid(CC / 32, NN / 32);                  // (32, 128)
    dim3 ggrid(CC / BN, NN / BM);                  // (4, 32) = 128 CTAs

    cvt_adj_kernel<<<(int)(((size_t)NN * NN) / (256 * 8)), 256>>>(adj, pAb);

    lin_kernel<<<lgrid, 256>>>(x, W0, pH, pHb, 0);
    gemm_ws_kernel<<<ggrid, 288, DSMEM>>>(pAb, pHb, pH, pO, nullptr, 0);

    lin_kernel<<<lgrid, 256>>>(pO, W1, pH, pHb, 1);
    gemm_ws_kernel<<<ggrid, 288, DSMEM>>>(pAb, pHb, pH, pO, nullptr, 0);

    lin_kernel<<<lgrid, 256>>>(pO, W2, pH, pHb, 1);
    gemm_ws_kernel<<<ggrid, 288, DSMEM>>>(pAb, pHb, pH, nullptr, out, 1);
}

// round 8
// speedup vs baseline: 3.1985x; 1.3071x over previous
#include <cuda_runtime.h>
#include <cuda_bf16.h>
#include <cstdint>

#define NN   4096
#define DD   16
#define CC   1024

// ---- GEMM tiling (R4-proven mainloop) ----
#define BM 128
#define BN 128
#define STAGES 4
#define KTILES 128            // K=4096 / BK=32
#define ASTG 8192             // A stage: 128 m-rows x 64 B
#define BSTG 8192             // B stage: 32 k-rows x 256 B
#define STGB (ASTG + BSTG)    // 16 KB
#define PIPE_B (STAGES*STGB)  // 64 KB
#define STAGE_PAD 129
#define EPI_B (128*STAGE_PAD*4)       // 66048
#define DSMEM (EPI_B > PIPE_B ? EPI_B : PIPE_B)

// ---- scratch: double-buffered H (fp32 identity) + Hb (bf16 B operand) ----
__device__ float          g_Hf0[(size_t)NN*CC];
__device__ float          g_Hf1[(size_t)NN*CC];
__device__ __nv_bfloat16  g_Hb0[(size_t)NN*CC];
__device__ __nv_bfloat16  g_Hb1[(size_t)NN*CC];
__device__ __nv_bfloat16  g_adjb[(size_t)NN*NN];

__device__ __forceinline__ uint32_t smem_u32(const void* p) {
    uint32_t a;
    asm("{ .reg .u64 t; cvta.to.shared.u64 t, %1; cvt.u32.u64 %0, t; }" : "=r"(a) : "l"(p));
    return a;
}
__device__ __forceinline__ void cp16(uint32_t dst, const void* src) {
    asm volatile("cp.async.cg.shared.global [%0], [%1], 16;" :: "r"(dst), "l"(src) : "memory");
}
// A: 64B rows, 4x16B chunks (R4-proven)
__device__ __forceinline__ uint32_t swzA(int r, int q) {
    return (uint32_t)((r << 6) + ((q ^ ((r >> 1) & 3)) << 4));
}
// B: 256B rows (k-major), 16x16B chunks; q ^= k&7 (conflict-free trans phases)
__device__ __forceinline__ uint32_t swzB(int k, int q) {
    return (uint32_t)((k << 8) + ((q ^ (k & 7)) << 4));
}

#define LDSM4(R, addr) \
    asm volatile("ldmatrix.sync.aligned.m8n8.x4.shared.b16 {%0,%1,%2,%3}, [%4];" \
        : "=r"((R)[0]), "=r"((R)[1]), "=r"((R)[2]), "=r"((R)[3]) : "r"(addr))
#define LDSM4T(R, addr) \
    asm volatile("ldmatrix.sync.aligned.m8n8.x4.trans.shared.b16 {%0,%1,%2,%3}, [%4];" \
        : "=r"((R)[0]), "=r"((R)[1]), "=r"((R)[2]), "=r"((R)[3]) : "r"(addr))

#define MMA(C, A_, B0, B1) \
    asm volatile("mma.sync.aligned.m16n8k16.row.col.f32.bf16.bf16.f32 " \
        "{%0,%1,%2,%3}, {%4,%5,%6,%7}, {%8,%9}, {%0,%1,%2,%3};" \
        : "+f"((C)[0]), "+f"((C)[1]), "+f"((C)[2]), "+f"((C)[3]) \
        : "r"((A_)[0]), "r"((A_)[1]), "r"((A_)[2]), "r"((A_)[3]), "r"(B0), "r"(B1))

// ===== fused0: blocks [0,8192): adj fp32->bf16; [8192,12288): lin layer0 =====
__global__ __launch_bounds__(256)
void fused0_kernel(const float* __restrict__ adj, __nv_bfloat16* __restrict__ Ab,
                   const float* __restrict__ X, const float* __restrict__ W,
                   float* __restrict__ Hf, __nv_bfloat16* __restrict__ Hb) {
    __shared__ float sW[DD][DD];
    __shared__ float sX[2][32][DD];
    const int t = threadIdx.x;

    if (blockIdx.x < 8192) {   // ---- cvt adj ----
        size_t idx = (size_t)blockIdx.x * 256 + t;
        const float4* src = reinterpret_cast<const float4*>(adj) + idx * 2;
        float4 a = src[0], b = src[1];
        union { __nv_bfloat162 h[4]; uint4 u; } pk;
        pk.h[0] = __floats2bfloat162_rn(a.x, a.y);
        pk.h[1] = __floats2bfloat162_rn(a.z, a.w);
        pk.h[2] = __floats2bfloat162_rn(b.x, b.y);
        pk.h[3] = __floats2bfloat162_rn(b.z, b.w);
        reinterpret_cast<uint4*>(Ab)[idx] = pk.u;
        return;
    }
    // ---- lin layer 0: X (b,n,d) -> Hf fp32 [m,c], Hb bf16 [m,c] ----
    const int bid = blockIdx.x - 8192;
    const int c0 = (bid & 31) * 32, m0 = (bid >> 5) * 32, b0 = c0 >> 4;

    sW[t >> 4][t & 15] = W[t];
    {
        int bloc = t >> 7, m = (t >> 2) & 31, seg = t & 3;
        const float* xp = X + ((size_t)(b0 + bloc) * NN + (m0 + m)) * DD + seg * 4;
        float4 v = *reinterpret_cast<const float4*>(xp);
        sX[bloc][m][seg*4]   = v.x; sX[bloc][m][seg*4+1] = v.y;
        sX[bloc][m][seg*4+2] = v.z; sX[bloc][m][seg*4+3] = v.w;
    }
    __syncthreads();
    {
        int m = t >> 3, quad = t & 7;
        int bloc = quad >> 2;
        int e0 = (quad & 3) * 4;
        float h[4] = {0.f, 0.f, 0.f, 0.f};
#pragma unroll
        for (int d = 0; d < DD; d++) {
            float xd = sX[bloc][m][d];
#pragma unroll
            for (int j = 0; j < 4; j++) h[j] = fmaf(xd, sW[d][e0 + j], h[j]);
        }
#pragma unroll
        for (int j = 0; j < 4; j++) h[j] = h[j] > 0.f ? h[j] : 0.2f * h[j];

        size_t off = (size_t)(m0 + m) * CC + c0 + quad * 4;
        *reinterpret_cast<float4*>(Hf + off) = make_float4(h[0], h[1], h[2], h[3]);
        union { __nv_bfloat162 p[2]; uint2 u; } pk;
        pk.p[0] = __floats2bfloat162_rn(h[0], h[1]);
        pk.p[1] = __floats2bfloat162_rn(h[2], h[3]);
        *reinterpret_cast<uint2*>(Hb + off) = pk.u;
    }
}

// ===== GEMM + fused next-layer linear:  o = adj@H + H;  h' = lrelu(o @ Wn) =====
// non-final: write Hf_out/Hb_out.  final: write Dout (b,n,d).
__global__ __launch_bounds__(128, 2)
void gemm_fused_kernel(const __nv_bfloat16* __restrict__ Ab,    // [4096,4096]
                       const __nv_bfloat16* __restrict__ Hb_in, // [4096,1024] k-major B
                       const float* __restrict__ Hf_in,         // [4096,1024] identity
                       const float* __restrict__ Wn,            // [16,16] or null
                       float* __restrict__ Hf_out,
                       __nv_bfloat16* __restrict__ Hb_out,
                       float* __restrict__ Dout,
                       int final_layer) {
    extern __shared__ char dsm[];
    __shared__ float sW[DD][DD + 1];
    const uint32_t sm = smem_u32(dsm);
    const int tid = threadIdx.x, wid = tid >> 5, l = tid & 31;
    const int bx = blockIdx.x, by = blockIdx.y;
    const int wm = wid >> 1, wn = wid & 1;

    if (!final_layer) {
        sW[tid >> 4][tid & 15] = Wn[tid & 255];
        if (tid < 128) sW[(tid + 128) >> 4][tid & 15] = Wn[128 + (tid & 127)];
    }

    const char* gA = (const char*)(Ab + (size_t)by * BM * NN);
    const char* gB = (const char*)Hb_in + (size_t)bx * BN * 2;

    // producer offsets: A 4x cp16 (R4 pattern), B 4x cp16
    const int rA = tid >> 2, qA = tid & 3;
    uint32_t offA[4]; size_t gOffA[4];
#pragma unroll
    for (int i = 0; i < 4; i++) {
        offA[i]  = swzA(rA + 32 * i, qA);
        gOffA[i] = (size_t)(rA + 32 * i) * 8192 + qA * 16;
    }
    uint32_t offB[4]; int kB[4], qB[4];
#pragma unroll
    for (int i = 0; i < 4; i++) {
        int idx = i * 128 + tid;
        kB[i] = idx >> 4; qB[i] = idx & 15;
        offB[i] = swzB(kB[i], qB[i]);
    }

#define LOAD_STAGE(s, kt) { \
    uint32_t sa = sm + (uint32_t)(s) * STGB; \
    const char* ga = gA + (size_t)(kt) * 64; \
    _Pragma("unroll") \
    for (int i_ = 0; i_ < 4; i_++) cp16(sa + offA[i_], ga + gOffA[i_]); \
    uint32_t sb = sa + ASTG; \
    const char* gb = gB + (size_t)(kt) * 32 * 2048; \
    _Pragma("unroll") \
    for (int i_ = 0; i_ < 4; i_++) \
        cp16(sb + offB[i_], gb + (size_t)kB[i_] * 2048 + qB[i_] * 16); }

    // consumer lane coords
    const int arow = wm * 64 + (l & 15);
    const int aqh  = l >> 4;
    const int g    = l >> 3;
    const int bk   = (g & 1) * 8 + (l & 7);
    const int bq   = wn * 8 + (g >> 1);

    float acc[4][8][4];
#pragma unroll
    for (int i = 0; i < 4; i++)
#pragma unroll
        for (int j = 0; j < 8; j++)
#pragma unroll
            for (int k = 0; k < 4; k++) acc[i][j][k] = 0.0f;

#pragma unroll
    for (int s = 0; s < STAGES - 1; s++) {
        LOAD_STAGE(s, s);
        asm volatile("cp.async.commit_group;" ::: "memory");
    }
    asm volatile("cp.async.wait_group %0;" :: "n"(STAGES - 2) : "memory");
    __syncthreads();

    uint32_t a[2][4][4], b[2][4][4];

#pragma unroll 1
    for (int kt = 0; kt < KTILES; kt++) {
        int pf = kt + STAGES - 1;
        if (pf < KTILES) { LOAD_STAGE(pf & (STAGES - 1), pf); }
        asm volatile("cp.async.commit_group;" ::: "memory");

        const uint32_t base  = sm + (uint32_t)(kt & (STAGES - 1)) * STGB;
        const uint32_t baseB = base + ASTG;

#pragma unroll
        for (int mi = 0; mi < 4; mi++)
            LDSM4(a[0][mi], base + swzA(arow + mi * 16, aqh));
#pragma unroll
        for (int nb = 0; nb < 4; nb++)
            LDSM4T(b[0][nb], baseB + swzB(bk, bq + nb * 2));

#pragma unroll
        for (int ks = 0; ks < 2; ks++) {
            if (ks == 0) {
#pragma unroll
                for (int mi = 0; mi < 4; mi++)
                    LDSM4(a[1][mi], base + swzA(arow + mi * 16, 2 + aqh));
#pragma unroll
                for (int nb = 0; nb < 4; nb++)
                    LDSM4T(b[1][nb], baseB + swzB(16 + bk, bq + nb * 2));
            }
#pragma unroll
            for (int mi = 0; mi < 4; mi++) {
#pragma unroll
                for (int nb = 0; nb < 4; nb++) {
                    const uint32_t* bb = b[ks][nb];
                    MMA(acc[mi][2*nb],   a[ks][mi], bb[0], bb[1]);
                    MMA(acc[mi][2*nb+1], a[ks][mi], bb[2], bb[3]);
                }
            }
        }
        asm volatile("cp.async.wait_group %0;" :: "n"(STAGES - 2) : "memory");
        __syncthreads();
    }
    asm volatile("cp.async.wait_group 0;" ::: "memory");
    __syncthreads();

    // ==== epilogue ====
    const int m0g = by * BM, c0g = bx * BN;

    if (final_layer) {
#pragma unroll
        for (int mi = 0; mi < 4; mi++) {
#pragma unroll
            for (int ni = 0; ni < 8; ni++) {
                int m = m0g + wm * 64 + mi * 16 + (l >> 2);
                int c = c0g + wn * 64 + ni * 8 + 2 * (l & 3);
                float2 i0 = *reinterpret_cast<const float2*>(Hf_in + (size_t)m * CC + c);
                float2 i1 = *reinterpret_cast<const float2*>(Hf_in + (size_t)(m + 8) * CC + c);
                float2 o0 = make_float2(acc[mi][ni][0] + i0.x, acc[mi][ni][1] + i0.y);
                float2 o1 = make_float2(acc[mi][ni][2] + i1.x, acc[mi][ni][3] + i1.y);
                int bq2 = c >> 4, d = c & 15;
                *reinterpret_cast<float2*>(Dout + ((size_t)bq2 * NN + m) * DD + d) = o0;
                *reinterpret_cast<float2*>(Dout + ((size_t)bq2 * NN + m + 8) * DD + d) = o1;
            }
        }
        return;
    }

    // stage o = acc + identity into smem [c][m] (pad 129)
    float* stage = reinterpret_cast<float*>(dsm);
#pragma unroll
    for (int mi = 0; mi < 4; mi++) {
#pragma unroll
        for (int ni = 0; ni < 8; ni++) {
            int mloc = wm * 64 + mi * 16 + (l >> 2);
            int cloc = wn * 64 + ni * 8 + 2 * (l & 3);
            int m = m0g + mloc, c = c0g + cloc;
            float2 i0 = *reinterpret_cast<const float2*>(Hf_in + (size_t)m * CC + c);
            float2 i1 = *reinterpret_cast<const float2*>(Hf_in + (size_t)(m + 8) * CC + c);
            stage[cloc * STAGE_PAD + mloc]           = acc[mi][ni][0] + i0.x;
            stage[(cloc + 1) * STAGE_PAD + mloc]     = acc[mi][ni][1] + i0.y;
            stage[cloc * STAGE_PAD + mloc + 8]       = acc[mi][ni][2] + i1.x;
            stage[(cloc + 1) * STAGE_PAD + mloc + 8] = acc[mi][ni][3] + i1.y;
        }
    }
    __syncthreads();

    // next-layer linear: thread -> (b = tid>>4, mlane = tid&15), 8 m-iters
    {
        const int bgrp = tid >> 4, mlane = tid & 15;
#pragma unroll
        for (int it = 0; it < 8; it++) {
            int mloc = mlane + 16 * it;
            float o[16];
#pragma unroll
            for (int d = 0; d < 16; d++)
                o[d] = stage[(bgrp * 16 + d) * STAGE_PAD + mloc];
            float h[16];
#pragma unroll
            for (int e = 0; e < 16; e++) h[e] = 0.0f;
#pragma unroll
            for (int d = 0; d < 16; d++) {
                float od = o[d];
#pragma unroll
                for (int e = 0; e < 16; e++) h[e] = fmaf(od, sW[d][e], h[e]);
            }
#pragma unroll
            for (int e = 0; e < 16; e++) h[e] = h[e] > 0.f ? h[e] : 0.2f * h[e];

            size_t off = (size_t)(m0g + mloc) * CC + c0g + bgrp * 16;
#pragma unroll
            for (int j = 0; j < 4; j++)
                *reinterpret_cast<float4*>(Hf_out + off + j * 4) =
                    make_float4(h[4*j], h[4*j+1], h[4*j+2], h[4*j+3]);
            union { __nv_bfloat162 p[4]; uint4 u; } pk;
#pragma unroll
            for (int j = 0; j < 4; j++) pk.p[j] = __floats2bfloat162_rn(h[2*j], h[2*j+1]);
            *reinterpret_cast<uint4*>(Hb_out + off) = pk.u;
#pragma unroll
            for (int j = 0; j < 4; j++) pk.p[j] = __floats2bfloat162_rn(h[8+2*j], h[9+2*j]);
            *reinterpret_cast<uint4*>(Hb_out + off + 8) = pk.u;
        }
    }
#undef LOAD_STAGE
}

// ================= launch =================
extern "C" void kernel_launch(void* const* d_in, const int* in_sizes, int n_in,
                              void* d_out, int out_size) {
    const float* x   = (const float*)d_in[0];
    const float* adj = (const float*)d_in[1];
    const float* W0  = (const float*)d_in[3];
    const float* W1  = (const float*)d_in[4];
    const float* W2  = (const float*)d_in[5];
    float* out = (float*)d_out;

    float *pHf0, *pHf1;
    __nv_bfloat16 *pHb0, *pHb1, *pAb;
    cudaGetSymbolAddress((void**)&pHf0, g_Hf0);
    cudaGetSymbolAddress((void**)&pHf1, g_Hf1);
    cudaGetSymbolAddress((void**)&pHb0, g_Hb0);
    cudaGetSymbolAddress((void**)&pHb1, g_Hb1);
    cudaGetSymbolAddress((void**)&pAb,  g_adjb);

    cudaFuncSetAttribute(gemm_fused_kernel, cudaFuncAttributeMaxDynamicSharedMemorySize, DSMEM);

    dim3 ggrid(CC / BN, NN / BM);                  // (8, 32) = 256 CTAs

    fused0_kernel<<<12288, 256>>>(adj, pAb, x, W0, pHf0, pHb0);
    // layer0 aggregate + layer1 linear
    gemm_fused_kernel<<<ggrid, 128, DSMEM>>>(pAb, pHb0, pHf0, W1, pHf1, pHb1, nullptr, 0);
    // layer1 aggregate + layer2 linear
    gemm_fused_kernel<<<ggrid, 128, DSMEM>>>(pAb, pHb1, pHf1, W2, pHf0, pHb0, nullptr, 0);
    // layer2 aggregate -> final output
    gemm_fused_kernel<<<ggrid, 128, DSMEM>>>(pAb, pHb0, pHf0, nullptr, nullptr, nullptr, out, 1);
}